// round 8
// baseline (speedup 1.0000x reference)
#include <cuda_runtime.h>
#include <cuda_fp16.h>
#include <cstdint>

#define M_ROWS   16384
#define F_DIM    1024
#define L_LAYERS 5

#define BM 128
#define BN 128
#define BK 32
#define NCHUNK (F_DIM / BK)   // 32
#define THREADS 512
#define STAGES 4

// smem: 3 tiles per stage (A, Bhi, Blo), each 128 rows x 32 fp16 (64B) padded to 80B rows.
#define ROW_BYTES   80
#define TILE_BYTES  (128 * ROW_BYTES)       // 10240
#define A_OFF       0u
#define BH_OFF      (1u * TILE_BYTES)
#define BL_OFF      (2u * TILE_BYTES)
#define STAGE_BYTES (3u * TILE_BYTES)       // 30720
#define SMEM_TOTAL  (STAGES * STAGE_BYTES)  // 122880

// ---------------- scratch ----------------
__device__ __half g_Bh[(size_t)L_LAYERS * F_DIM * F_DIM];  // 10 MB  (W*adj)^T hi
__device__ __half g_Bl[(size_t)L_LAYERS * F_DIM * F_DIM];  // 10 MB  (W*adj)^T lo
__device__ __half g_A [(size_t)M_ROWS * F_DIM];            // 32 MB  current h (fp16)
__device__ float g_bufA[(size_t)M_ROWS * F_DIM];           // 64 MB  ypre
__device__ float g_bufB[(size_t)M_ROWS * F_DIM];           // 64 MB  normalized h (fp32)

// ---------------- helpers ----------------
__device__ __forceinline__ uint32_t smem_u32(const void* p) {
    uint32_t a;
    asm("{ .reg .u64 t; cvta.to.shared.u64 t, %1; cvt.u32.u64 %0, t; }" : "=r"(a) : "l"(p));
    return a;
}
__device__ __forceinline__ void cp_async16(uint32_t dst, const void* src) {
    asm volatile("cp.async.cg.shared.global [%0], [%1], 16;" :: "r"(dst), "l"(src));
}
#define CP_COMMIT()  asm volatile("cp.async.commit_group;")
#define CP_WAIT(n)   asm volatile("cp.async.wait_group %0;" :: "n"(n))

#define LDSM_X4(r, addr) \
    asm volatile("ldmatrix.sync.aligned.m8n8.x4.shared.b16 {%0,%1,%2,%3}, [%4];" \
        : "=r"((r)[0]), "=r"((r)[1]), "=r"((r)[2]), "=r"((r)[3]) : "r"(addr))

// fp32-accumulator MMA (main term)
__device__ __forceinline__ void mma_f32acc(float* d, const uint32_t* a,
                                           uint32_t b0, uint32_t b1) {
    asm volatile(
        "mma.sync.aligned.m16n8k16.row.col.f32.f16.f16.f32 "
        "{%0,%1,%2,%3}, {%4,%5,%6,%7}, {%8,%9}, {%0,%1,%2,%3};"
        : "+f"(d[0]), "+f"(d[1]), "+f"(d[2]), "+f"(d[3])
        : "r"(a[0]), "r"(a[1]), "r"(a[2]), "r"(a[3]), "r"(b0), "r"(b1));
}
// fp16-accumulator MMA (lo correction term; values ~2^-11, fp16 acc safe)
__device__ __forceinline__ void mma_f16acc(uint32_t* d, const uint32_t* a,
                                           uint32_t b0, uint32_t b1) {
    asm volatile(
        "mma.sync.aligned.m16n8k16.row.col.f16.f16.f16.f16 "
        "{%0,%1}, {%2,%3,%4,%5}, {%6,%7}, {%0,%1};"
        : "+r"(d[0]), "+r"(d[1])
        : "r"(a[0]), "r"(a[1]), "r"(a[2]), "r"(a[3]), "r"(b0), "r"(b1));
}

// ---------------- prep: B{h,l}[l][n][k] = split_fp16(W[l][k][n] * adj[k][n]) ----------------
__global__ void prep_kernel(const float* __restrict__ W, const float* __restrict__ adj) {
    __shared__ float tile[32][33];
    const int l = blockIdx.z;
    const int kb = blockIdx.x * 32;
    const int nb = blockIdx.y * 32;
    #pragma unroll
    for (int i = 0; i < 4; i++) {
        int k = kb + threadIdx.y + i * 8;
        int n = nb + threadIdx.x;
        tile[threadIdx.y + i * 8][threadIdx.x] =
            W[((size_t)l * F_DIM + k) * F_DIM + n] * adj[(size_t)k * F_DIM + n];
    }
    __syncthreads();
    #pragma unroll
    for (int i = 0; i < 4; i++) {
        int n = nb + threadIdx.y + i * 8;
        int k = kb + threadIdx.x;
        float v = tile[threadIdx.x][threadIdx.y + i * 8];
        __half h = __float2half(v);
        float rem = v - __half2float(h);
        size_t o = ((size_t)l * F_DIM + n) * F_DIM + k;
        g_Bh[o] = h;
        g_Bl[o] = __float2half(rem);
    }
}

// ---------------- x -> fp16 (two launches so ncu -s 5 hits gemm layer 1) ----
__global__ void tohalf_kernel(const float* __restrict__ X, size_t off4) {
    size_t idx = off4 + (size_t)blockIdx.x * blockDim.x + threadIdx.x;
    float4 v = ((const float4*)X)[idx];
    __half2 p0{__float2half(v.x), __float2half(v.y)};
    __half2 p1{__float2half(v.z), __float2half(v.w)};
    uint2 u;
    u.x = *(uint32_t*)&p0; u.y = *(uint32_t*)&p1;
    ((uint2*)g_A)[idx] = u;
}

// ---------------- GEMM: Y = relu(A @ (Bh+Bl) + bias) + Hres ----------------
__global__ void __launch_bounds__(THREADS, 1)
gemm_mma_kernel(const __half* __restrict__ A, const float* __restrict__ Hres,
                const __half* __restrict__ Bh, const __half* __restrict__ Bl,
                const float* __restrict__ bias, float* __restrict__ Y)
{
    extern __shared__ char smem[];
    const uint32_t sb = smem_u32(smem);
    const int tid = threadIdx.x;
    const int wid = tid >> 5;
    const int lid = tid & 31;
    const int warpM = wid & 3;     // 4 warps in M, tile 32 rows
    const int warpN = wid >> 2;    // 4 warps in N, tile 32 cols
    const int skew  = (wid >> 3) & 1;  // warps 8-15 process kh in reverse order
    const int blockRow = blockIdx.y * BM;
    const int blockCol = blockIdx.x * BN;

    const char* gA  = (const char*)(A  + (size_t)blockRow * F_DIM);
    const char* gBh = (const char*)(Bh + (size_t)blockCol * F_DIM);
    const char* gBl = (const char*)(Bl + (size_t)blockCol * F_DIM);

    // 16B chunks: tile = 128 rows x 4 chunks = 512; 512 threads -> 1 per tile
    auto load_stage = [&](int c, int s) {
        const int k0b = c * BK * 2;
        const uint32_t base = sb + (uint32_t)s * STAGE_BYTES;
        const int r = tid >> 2;
        const int c16 = tid & 3;
        const uint32_t soff = (uint32_t)(r * ROW_BYTES + c16 * 16);
        const size_t goff = (size_t)r * (F_DIM * 2) + k0b + c16 * 16;
        cp_async16(base + A_OFF  + soff, gA  + goff);
        cp_async16(base + BH_OFF + soff, gBh + goff);
        cp_async16(base + BL_OFF + soff, gBl + goff);
    };

    float    acc [2][4][4];   // fp32 acc for A@Bh
    uint32_t acch[2][4][2];   // fp16 acc (half2 x2) for A@Bl
    #pragma unroll
    for (int mt = 0; mt < 2; mt++)
        #pragma unroll
        for (int nt = 0; nt < 4; nt++) {
            #pragma unroll
            for (int i = 0; i < 4; i++) acc[mt][nt][i] = 0.f;
            acch[mt][nt][0] = 0u; acch[mt][nt][1] = 0u;
        }

    load_stage(0, 0); CP_COMMIT();
    load_stage(1, 1); CP_COMMIT();
    load_stage(2, 2); CP_COMMIT();

    const uint32_t aRowOff = (uint32_t)((warpM * 32 + (lid & 15)) * ROW_BYTES + ((lid >> 4) << 4));
    const uint32_t bRowOff = (uint32_t)((warpN * 32 + (lid & 15)) * ROW_BYTES + ((lid >> 4) << 4));

    for (int c = 0; c < NCHUNK; ++c) {
        CP_WAIT(2);
        __syncthreads();
        if (c + 3 < NCHUNK) load_stage(c + 3, (c + 3) & 3);
        CP_COMMIT();

        const uint32_t stage = sb + (uint32_t)(c & 3) * STAGE_BYTES;
        #pragma unroll
        for (int kk = 0; kk < 2; kk++) {
            // warp skew: half the warps take kh=0 then 1, the other half 1 then 0.
            // Overlaps LSU (ldmatrix) phase of one half with tensor phase of the other.
            const int kh = skew ? (1 - kk) : kk;
            const uint32_t kb = (uint32_t)(kh * 32);  // 16 fp16 = 32B
            uint32_t a[2][4], bh[2][4], bl[2][4];
            #pragma unroll
            for (int mt = 0; mt < 2; mt++)
                LDSM_X4(a[mt], stage + A_OFF + aRowOff + (uint32_t)(mt * 16 * ROW_BYTES) + kb);
            #pragma unroll
            for (int g = 0; g < 2; g++) {
                LDSM_X4(bh[g], stage + BH_OFF + bRowOff + (uint32_t)(g * 16 * ROW_BYTES) + kb);
                LDSM_X4(bl[g], stage + BL_OFF + bRowOff + (uint32_t)(g * 16 * ROW_BYTES) + kb);
            }
            // main term (fp32 acc)
            #pragma unroll
            for (int mt = 0; mt < 2; mt++)
                #pragma unroll
                for (int nt = 0; nt < 4; nt++) {
                    const int g = nt >> 1, h = nt & 1;
                    mma_f32acc(acc[mt][nt], a[mt], bh[g][h], bh[g][h + 2]);
                }
            // lo correction (fp16 acc)
            #pragma unroll
            for (int mt = 0; mt < 2; mt++)
                #pragma unroll
                for (int nt = 0; nt < 4; nt++) {
                    const int g = nt >> 1, h = nt & 1;
                    mma_f16acc(acch[mt][nt], a[mt], bl[g][h], bl[g][h + 2]);
                }
        }
    }

    // ---- epilogue: merge lo acc, bias + relu + residual ----
    const int lane4 = lid >> 2;
    const int lanec = (lid & 3) * 2;
    float2 bv[4];
    #pragma unroll
    for (int nt = 0; nt < 4; nt++)
        bv[nt] = *(const float2*)(bias + blockCol + warpN * 32 + nt * 8 + lanec);

    #pragma unroll
    for (int mt = 0; mt < 2; mt++) {
        const int r0 = blockRow + warpM * 32 + mt * 16 + lane4;
        const int r1 = r0 + 8;
        #pragma unroll
        for (int nt = 0; nt < 4; nt++) {
            const int col = blockCol + warpN * 32 + nt * 8 + lanec;
            const size_t o0 = (size_t)r0 * F_DIM + col;
            const size_t o1 = (size_t)r1 * F_DIM + col;
            float2 h0 = *(const float2*)(Hres + o0);
            float2 h1 = *(const float2*)(Hres + o1);
            float* a4 = acc[mt][nt];
            __half2 c0 = *(__half2*)&acch[mt][nt][0];
            __half2 c1 = *(__half2*)&acch[mt][nt][1];
            float s0 = a4[0] + __low2float(c0);
            float s1 = a4[1] + __high2float(c0);
            float s2 = a4[2] + __low2float(c1);
            float s3 = a4[3] + __high2float(c1);
            float2 y0, y1;
            y0.x = fmaxf(s0 + bv[nt].x, 0.f) + h0.x;
            y0.y = fmaxf(s1 + bv[nt].y, 0.f) + h0.y;
            y1.x = fmaxf(s2 + bv[nt].x, 0.f) + h1.x;
            y1.y = fmaxf(s3 + bv[nt].y, 0.f) + h1.y;
            *(float2*)(Y + o0) = y0;
            *(float2*)(Y + o1) = y1;
        }
    }
}

// ---------------- LayerNorm (+ optional fp16 store for next layer's A) ----------------
__global__ void ln_split_kernel(const float* __restrict__ Yin, float* __restrict__ Yout,
                                int do_half) {
    const int row = blockIdx.x;
    const size_t base4 = (size_t)row * (F_DIM / 4);
    float4 v = ((const float4*)Yin)[base4 + threadIdx.x];
    float s  = v.x + v.y + v.z + v.w;
    float ss = v.x * v.x + v.y * v.y + v.z * v.z + v.w * v.w;
    #pragma unroll
    for (int o = 16; o > 0; o >>= 1) {
        s  += __shfl_down_sync(0xffffffffu, s,  o);
        ss += __shfl_down_sync(0xffffffffu, ss, o);
    }
    __shared__ float sh_s[8], sh_ss[8];
    const int warp = threadIdx.x >> 5, lane = threadIdx.x & 31;
    if (lane == 0) { sh_s[warp] = s; sh_ss[warp] = ss; }
    __syncthreads();
    float st = 0.f, sst = 0.f;
    #pragma unroll
    for (int w = 0; w < 8; w++) { st += sh_s[w]; sst += sh_ss[w]; }
    const float inv = 1.0f / (float)F_DIM;
    const float mu  = st * inv;
    const float var = sst * inv - mu * mu;
    const float r   = rsqrtf(var + 1e-5f);
    v.x = (v.x - mu) * r; v.y = (v.y - mu) * r;
    v.z = (v.z - mu) * r; v.w = (v.w - mu) * r;
    ((float4*)Yout)[base4 + threadIdx.x] = v;
    if (do_half) {
        __half2 p0{__float2half(v.x), __float2half(v.y)};
        __half2 p1{__float2half(v.z), __float2half(v.w)};
        uint2 u;
        u.x = *(uint32_t*)&p0; u.y = *(uint32_t*)&p1;
        ((uint2*)g_A)[base4 + threadIdx.x] = u;
    }
}

// ---------------- launch ----------------
extern "C" void kernel_launch(void* const* d_in, const int* in_sizes, int n_in,
                              void* d_out, int out_size) {
    const float* x    = (const float*)d_in[0];   // (16384, 1024)
    const float* adj  = (const float*)d_in[1];   // (1024, 1024)
    const float* W    = (const float*)d_in[2];   // (5, 1024, 1024)
    const float* bias = (const float*)d_in[3];   // (5, 1024)
    float* out = (float*)d_out;

    cudaFuncSetAttribute(gemm_mma_kernel,
                         cudaFuncAttributeMaxDynamicSharedMemorySize, SMEM_TOTAL);

    __half *bh, *bl, *ah;
    float *bufA, *bufB;
    cudaGetSymbolAddress((void**)&bh,   g_Bh);
    cudaGetSymbolAddress((void**)&bl,   g_Bl);
    cudaGetSymbolAddress((void**)&ah,   g_A);
    cudaGetSymbolAddress((void**)&bufA, g_bufA);
    cudaGetSymbolAddress((void**)&bufB, g_bufB);

    prep_kernel<<<dim3(F_DIM / 32, F_DIM / 32, L_LAYERS), dim3(32, 8)>>>(W, adj);
    const size_t half4 = (size_t)M_ROWS * F_DIM / 4 / 2;
    tohalf_kernel<<<(int)(half4 / 256), 256>>>(x, 0);
    tohalf_kernel<<<(int)(half4 / 256), 256>>>(x, half4);

    const float* h = x;
    for (int l = 0; l < L_LAYERS; ++l) {
        const size_t bo = (size_t)l * F_DIM * F_DIM;
        gemm_mma_kernel<<<dim3(F_DIM / BN, M_ROWS / BM), THREADS, SMEM_TOTAL>>>(
            ah, h, bh + bo, bl + bo, bias + (size_t)l * F_DIM, bufA);
        const int last = (l == L_LAYERS - 1);
        ln_split_kernel<<<M_ROWS, 256>>>(bufA, last ? out : bufB, !last);
        h = bufB;
    }
}

// round 9
// speedup vs baseline: 1.0105x; 1.0105x over previous
#include <cuda_runtime.h>
#include <cuda_fp16.h>
#include <cstdint>

#define M_ROWS   16384
#define F_DIM    1024
#define L_LAYERS 5

#define BM 128
#define BN 64
#define BK 32
#define NCHUNK (F_DIM / BK)   // 32
#define THREADS 256
#define STAGES 4

// smem per stage: A 128x32 fp16 rows padded to 80B; Bh,Bl 64x32 fp16 rows padded 80B.
#define ROW_BYTES   80
#define A_TILE      (128 * ROW_BYTES)       // 10240
#define B_TILE      (64 * ROW_BYTES)        // 5120
#define A_OFF       0u
#define BH_OFF      (A_TILE)
#define BL_OFF      (A_TILE + B_TILE)
#define STAGE_BYTES (A_TILE + 2 * B_TILE)   // 20480
#define SMEM_TOTAL  (STAGES * STAGE_BYTES)  // 81920  (x2 CTAs = 160K <= 227K)

// ---------------- scratch ----------------
__device__ __half g_Bh[(size_t)L_LAYERS * F_DIM * F_DIM];  // 10 MB
__device__ __half g_Bl[(size_t)L_LAYERS * F_DIM * F_DIM];  // 10 MB
__device__ __half g_A [(size_t)M_ROWS * F_DIM];            // 32 MB
__device__ float g_bufA[(size_t)M_ROWS * F_DIM];           // 64 MB
__device__ float g_bufB[(size_t)M_ROWS * F_DIM];           // 64 MB

// ---------------- helpers ----------------
__device__ __forceinline__ uint32_t smem_u32(const void* p) {
    uint32_t a;
    asm("{ .reg .u64 t; cvta.to.shared.u64 t, %1; cvt.u32.u64 %0, t; }" : "=r"(a) : "l"(p));
    return a;
}
__device__ __forceinline__ void cp_async16(uint32_t dst, const void* src) {
    asm volatile("cp.async.cg.shared.global [%0], [%1], 16;" :: "r"(dst), "l"(src));
}
#define CP_COMMIT()  asm volatile("cp.async.commit_group;")
#define CP_WAIT(n)   asm volatile("cp.async.wait_group %0;" :: "n"(n))

#define LDSM_X4(r, addr) \
    asm volatile("ldmatrix.sync.aligned.m8n8.x4.shared.b16 {%0,%1,%2,%3}, [%4];" \
        : "=r"((r)[0]), "=r"((r)[1]), "=r"((r)[2]), "=r"((r)[3]) : "r"(addr))

__device__ __forceinline__ void mma_f32acc(float* d, const uint32_t* a,
                                           uint32_t b0, uint32_t b1) {
    asm volatile(
        "mma.sync.aligned.m16n8k16.row.col.f32.f16.f16.f32 "
        "{%0,%1,%2,%3}, {%4,%5,%6,%7}, {%8,%9}, {%0,%1,%2,%3};"
        : "+f"(d[0]), "+f"(d[1]), "+f"(d[2]), "+f"(d[3])
        : "r"(a[0]), "r"(a[1]), "r"(a[2]), "r"(a[3]), "r"(b0), "r"(b1));
}
__device__ __forceinline__ void mma_f16acc(uint32_t* d, const uint32_t* a,
                                           uint32_t b0, uint32_t b1) {
    asm volatile(
        "mma.sync.aligned.m16n8k16.row.col.f16.f16.f16.f16 "
        "{%0,%1}, {%2,%3,%4,%5}, {%6,%7}, {%0,%1};"
        : "+r"(d[0]), "+r"(d[1])
        : "r"(a[0]), "r"(a[1]), "r"(a[2]), "r"(a[3]), "r"(b0), "r"(b1));
}

// ---------------- prep: B{h,l}[l][n][k] = split_fp16(W[l][k][n] * adj[k][n]) ----------------
__global__ void prep_kernel(const float* __restrict__ W, const float* __restrict__ adj) {
    __shared__ float tile[32][33];
    const int l = blockIdx.z;
    const int kb = blockIdx.x * 32;
    const int nb = blockIdx.y * 32;
    #pragma unroll
    for (int i = 0; i < 4; i++) {
        int k = kb + threadIdx.y + i * 8;
        int n = nb + threadIdx.x;
        tile[threadIdx.y + i * 8][threadIdx.x] =
            W[((size_t)l * F_DIM + k) * F_DIM + n] * adj[(size_t)k * F_DIM + n];
    }
    __syncthreads();
    #pragma unroll
    for (int i = 0; i < 4; i++) {
        int n = nb + threadIdx.y + i * 8;
        int k = kb + threadIdx.x;
        float v = tile[threadIdx.x][threadIdx.y + i * 8];
        __half h = __float2half(v);
        float rem = v - __half2float(h);
        size_t o = ((size_t)l * F_DIM + n) * F_DIM + k;
        g_Bh[o] = h;
        g_Bl[o] = __float2half(rem);
    }
}

// ---------------- x -> fp16 (two launches so ncu -s 5 lands inside the layer loop) ----
__global__ void tohalf_kernel(const float* __restrict__ X, size_t off4) {
    size_t idx = off4 + (size_t)blockIdx.x * blockDim.x + threadIdx.x;
    float4 v = ((const float4*)X)[idx];
    __half2 p0{__float2half(v.x), __float2half(v.y)};
    __half2 p1{__float2half(v.z), __float2half(v.w)};
    uint2 u;
    u.x = *(uint32_t*)&p0; u.y = *(uint32_t*)&p1;
    ((uint2*)g_A)[idx] = u;
}

// ---------------- GEMM: Y = relu(A @ (Bh+Bl) + bias) + Hres ----------------
__global__ void __launch_bounds__(THREADS, 2)
gemm_mma_kernel(const __half* __restrict__ A, const float* __restrict__ Hres,
                const __half* __restrict__ Bh, const __half* __restrict__ Bl,
                const float* __restrict__ bias, float* __restrict__ Y)
{
    extern __shared__ char smem[];
    const uint32_t sb = smem_u32(smem);
    const int tid = threadIdx.x;
    const int wid = tid >> 5;
    const int lid = tid & 31;
    const int warpM = wid & 3;     // 4 warps in M, tile 32 rows
    const int warpN = wid >> 2;    // 2 warps in N, tile 32 cols
    const int blockRow = blockIdx.y * BM;
    const int blockCol = blockIdx.x * BN;

    const char* gA  = (const char*)(A  + (size_t)blockRow * F_DIM);
    const char* gBh = (const char*)(Bh + (size_t)blockCol * F_DIM);
    const char* gBl = (const char*)(Bl + (size_t)blockCol * F_DIM);

    // per stage: A = 512 x 16B chunks (2/thread), Bh = 256 (1/thread), Bl = 256 (1/thread)
    auto load_stage = [&](int c, int s) {
        const int k0b = c * BK * 2;
        const uint32_t base = sb + (uint32_t)s * STAGE_BYTES;
        #pragma unroll
        for (int i = 0; i < 2; i++) {
            const int u = tid + 256 * i;
            const int r = u >> 2;
            const int c16 = u & 3;
            cp_async16(base + A_OFF + (uint32_t)(r * ROW_BYTES + c16 * 16),
                       gA + (size_t)r * (F_DIM * 2) + k0b + c16 * 16);
        }
        const int rb = tid >> 2;
        const int cb = tid & 3;
        const uint32_t bso = (uint32_t)(rb * ROW_BYTES + cb * 16);
        const size_t bgo = (size_t)rb * (F_DIM * 2) + k0b + cb * 16;
        cp_async16(base + BH_OFF + bso, gBh + bgo);
        cp_async16(base + BL_OFF + bso, gBl + bgo);
    };

    float    acc [2][4][4];   // fp32 acc for A@Bh
    uint32_t acch[2][4][2];   // fp16 acc for A@Bl (correction, |vals| ~2^-11)
    #pragma unroll
    for (int mt = 0; mt < 2; mt++)
        #pragma unroll
        for (int nt = 0; nt < 4; nt++) {
            #pragma unroll
            for (int i = 0; i < 4; i++) acc[mt][nt][i] = 0.f;
            acch[mt][nt][0] = 0u; acch[mt][nt][1] = 0u;
        }

    load_stage(0, 0); CP_COMMIT();
    load_stage(1, 1); CP_COMMIT();
    load_stage(2, 2); CP_COMMIT();

    const uint32_t aRowOff = (uint32_t)((warpM * 32 + (lid & 15)) * ROW_BYTES + ((lid >> 4) << 4));
    const uint32_t bRowOff = (uint32_t)((warpN * 32 + (lid & 15)) * ROW_BYTES + ((lid >> 4) << 4));

    for (int c = 0; c < NCHUNK; ++c) {
        CP_WAIT(2);
        __syncthreads();
        if (c + 3 < NCHUNK) load_stage(c + 3, (c + 3) & 3);
        CP_COMMIT();

        const uint32_t stage = sb + (uint32_t)(c & 3) * STAGE_BYTES;
        #pragma unroll
        for (int kh = 0; kh < 2; kh++) {
            const uint32_t kb = (uint32_t)(kh * 32);  // 16 fp16 = 32B
            uint32_t a[2][4], bh[2][4], bl[2][4];
            #pragma unroll
            for (int mt = 0; mt < 2; mt++)
                LDSM_X4(a[mt], stage + A_OFF + aRowOff + (uint32_t)(mt * 16 * ROW_BYTES) + kb);
            #pragma unroll
            for (int g = 0; g < 2; g++) {
                LDSM_X4(bh[g], stage + BH_OFF + bRowOff + (uint32_t)(g * 16 * ROW_BYTES) + kb);
                LDSM_X4(bl[g], stage + BL_OFF + bRowOff + (uint32_t)(g * 16 * ROW_BYTES) + kb);
            }
            #pragma unroll
            for (int mt = 0; mt < 2; mt++)
                #pragma unroll
                for (int nt = 0; nt < 4; nt++) {
                    const int g = nt >> 1, h = nt & 1;
                    mma_f32acc(acc[mt][nt], a[mt], bh[g][h], bh[g][h + 2]);
                }
            #pragma unroll
            for (int mt = 0; mt < 2; mt++)
                #pragma unroll
                for (int nt = 0; nt < 4; nt++) {
                    const int g = nt >> 1, h = nt & 1;
                    mma_f16acc(acch[mt][nt], a[mt], bl[g][h], bl[g][h + 2]);
                }
        }
    }

    // ---- epilogue: merge lo acc, bias + relu + residual ----
    const int lane4 = lid >> 2;
    const int lanec = (lid & 3) * 2;
    float2 bv[4];
    #pragma unroll
    for (int nt = 0; nt < 4; nt++)
        bv[nt] = *(const float2*)(bias + blockCol + warpN * 32 + nt * 8 + lanec);

    #pragma unroll
    for (int mt = 0; mt < 2; mt++) {
        const int r0 = blockRow + warpM * 32 + mt * 16 + lane4;
        const int r1 = r0 + 8;
        #pragma unroll
        for (int nt = 0; nt < 4; nt++) {
            const int col = blockCol + warpN * 32 + nt * 8 + lanec;
            const size_t o0 = (size_t)r0 * F_DIM + col;
            const size_t o1 = (size_t)r1 * F_DIM + col;
            float2 h0 = *(const float2*)(Hres + o0);
            float2 h1 = *(const float2*)(Hres + o1);
            float* a4 = acc[mt][nt];
            __half2 c0 = *(__half2*)&acch[mt][nt][0];
            __half2 c1 = *(__half2*)&acch[mt][nt][1];
            float s0 = a4[0] + __low2float(c0);
            float s1 = a4[1] + __high2float(c0);
            float s2 = a4[2] + __low2float(c1);
            float s3 = a4[3] + __high2float(c1);
            float2 y0, y1;
            y0.x = fmaxf(s0 + bv[nt].x, 0.f) + h0.x;
            y0.y = fmaxf(s1 + bv[nt].y, 0.f) + h0.y;
            y1.x = fmaxf(s2 + bv[nt].x, 0.f) + h1.x;
            y1.y = fmaxf(s3 + bv[nt].y, 0.f) + h1.y;
            *(float2*)(Y + o0) = y0;
            *(float2*)(Y + o1) = y1;
        }
    }
}

// ---------------- LayerNorm (+ optional fp16 store for next layer's A) ----------------
__global__ void ln_split_kernel(const float* __restrict__ Yin, float* __restrict__ Yout,
                                int do_half) {
    const int row = blockIdx.x;
    const size_t base4 = (size_t)row * (F_DIM / 4);
    float4 v = ((const float4*)Yin)[base4 + threadIdx.x];
    float s  = v.x + v.y + v.z + v.w;
    float ss = v.x * v.x + v.y * v.y + v.z * v.z + v.w * v.w;
    #pragma unroll
    for (int o = 16; o > 0; o >>= 1) {
        s  += __shfl_down_sync(0xffffffffu, s,  o);
        ss += __shfl_down_sync(0xffffffffu, ss, o);
    }
    __shared__ float sh_s[8], sh_ss[8];
    const int warp = threadIdx.x >> 5, lane = threadIdx.x & 31;
    if (lane == 0) { sh_s[warp] = s; sh_ss[warp] = ss; }
    __syncthreads();
    float st = 0.f, sst = 0.f;
    #pragma unroll
    for (int w = 0; w < 8; w++) { st += sh_s[w]; sst += sh_ss[w]; }
    const float inv = 1.0f / (float)F_DIM;
    const float mu  = st * inv;
    const float var = sst * inv - mu * mu;
    const float r   = rsqrtf(var + 1e-5f);
    v.x = (v.x - mu) * r; v.y = (v.y - mu) * r;
    v.z = (v.z - mu) * r; v.w = (v.w - mu) * r;
    ((float4*)Yout)[base4 + threadIdx.x] = v;
    if (do_half) {
        __half2 p0{__float2half(v.x), __float2half(v.y)};
        __half2 p1{__float2half(v.z), __float2half(v.w)};
        uint2 u;
        u.x = *(uint32_t*)&p0; u.y = *(uint32_t*)&p1;
        ((uint2*)g_A)[base4 + threadIdx.x] = u;
    }
}

// ---------------- launch ----------------
extern "C" void kernel_launch(void* const* d_in, const int* in_sizes, int n_in,
                              void* d_out, int out_size) {
    const float* x    = (const float*)d_in[0];   // (16384, 1024)
    const float* adj  = (const float*)d_in[1];   // (1024, 1024)
    const float* W    = (const float*)d_in[2];   // (5, 1024, 1024)
    const float* bias = (const float*)d_in[3];   // (5, 1024)
    float* out = (float*)d_out;

    cudaFuncSetAttribute(gemm_mma_kernel,
                         cudaFuncAttributeMaxDynamicSharedMemorySize, SMEM_TOTAL);

    __half *bh, *bl, *ah;
    float *bufA, *bufB;
    cudaGetSymbolAddress((void**)&bh,   g_Bh);
    cudaGetSymbolAddress((void**)&bl,   g_Bl);
    cudaGetSymbolAddress((void**)&ah,   g_A);
    cudaGetSymbolAddress((void**)&bufA, g_bufA);
    cudaGetSymbolAddress((void**)&bufB, g_bufB);

    prep_kernel<<<dim3(F_DIM / 32, F_DIM / 32, L_LAYERS), dim3(32, 8)>>>(W, adj);
    const size_t half4 = (size_t)M_ROWS * F_DIM / 4 / 2;
    tohalf_kernel<<<(int)(half4 / 256), 256>>>(x, 0);
    tohalf_kernel<<<(int)(half4 / 256), 256>>>(x, half4);

    const float* h = x;
    for (int l = 0; l < L_LAYERS; ++l) {
        const size_t bo = (size_t)l * F_DIM * F_DIM;
        gemm_mma_kernel<<<dim3(F_DIM / BN, M_ROWS / BM), THREADS, SMEM_TOTAL>>>(
            ah, h, bh + bo, bl + bo, bias + (size_t)l * F_DIM, bufA);
        const int last = (l == L_LAYERS - 1);
        ln_split_kernel<<<M_ROWS, 256>>>(bufA, last ? out : bufB, !last);
        h = bufB;
    }
}

// round 10
// speedup vs baseline: 1.0331x; 1.0224x over previous
#include <cuda_runtime.h>
#include <cuda_fp16.h>
#include <cstdint>

#define M_ROWS   16384
#define F_DIM    1024
#define L_LAYERS 5

#define BM 128
#define BN 128
#define BK 32
#define NCHUNK (F_DIM / BK)   // 32
#define THREADS 256
#define STAGES 3

// smem per stage: A, Bh, Bl each 128 rows x 32 fp16 (64B) padded to 80B rows.
#define ROW_BYTES   80
#define TILE_BYTES  (128 * ROW_BYTES)       // 10240
#define A_OFF       0u
#define BH_OFF      (1u * TILE_BYTES)
#define BL_OFF      (2u * TILE_BYTES)
#define STAGE_BYTES (3u * TILE_BYTES)       // 30720
#define SMEM_TOTAL  (STAGES * STAGE_BYTES)  // 92160 (x2 CTAs = 184320 <= 227KB)

// ---------------- scratch ----------------
__device__ __half g_Bh[(size_t)L_LAYERS * F_DIM * F_DIM];  // 10 MB
__device__ __half g_Bl[(size_t)L_LAYERS * F_DIM * F_DIM];  // 10 MB
__device__ __half g_A [(size_t)M_ROWS * F_DIM];            // 32 MB
__device__ float g_bufA[(size_t)M_ROWS * F_DIM];           // 64 MB
__device__ float g_bufB[(size_t)M_ROWS * F_DIM];           // 64 MB

// ---------------- helpers ----------------
__device__ __forceinline__ uint32_t smem_u32(const void* p) {
    uint32_t a;
    asm("{ .reg .u64 t; cvta.to.shared.u64 t, %1; cvt.u32.u64 %0, t; }" : "=r"(a) : "l"(p));
    return a;
}
__device__ __forceinline__ void cp_async16(uint32_t dst, const void* src) {
    asm volatile("cp.async.cg.shared.global [%0], [%1], 16;" :: "r"(dst), "l"(src));
}
#define CP_COMMIT()  asm volatile("cp.async.commit_group;")
#define CP_WAIT(n)   asm volatile("cp.async.wait_group %0;" :: "n"(n))

#define LDSM_X4(r, addr) \
    asm volatile("ldmatrix.sync.aligned.m8n8.x4.shared.b16 {%0,%1,%2,%3}, [%4];" \
        : "=r"((r)[0]), "=r"((r)[1]), "=r"((r)[2]), "=r"((r)[3]) : "r"(addr))

__device__ __forceinline__ void mma_f32acc(float* d, const uint32_t* a,
                                           uint32_t b0, uint32_t b1) {
    asm volatile(
        "mma.sync.aligned.m16n8k16.row.col.f32.f16.f16.f32 "
        "{%0,%1,%2,%3}, {%4,%5,%6,%7}, {%8,%9}, {%0,%1,%2,%3};"
        : "+f"(d[0]), "+f"(d[1]), "+f"(d[2]), "+f"(d[3])
        : "r"(a[0]), "r"(a[1]), "r"(a[2]), "r"(a[3]), "r"(b0), "r"(b1));
}

// ---------------- prep: B{h,l}[l][n][k] = split_fp16(W[l][k][n] * adj[k][n]) ----------------
__global__ void prep_kernel(const float* __restrict__ W, const float* __restrict__ adj) {
    __shared__ float tile[32][33];
    const int l = blockIdx.z;
    const int kb = blockIdx.x * 32;
    const int nb = blockIdx.y * 32;
    #pragma unroll
    for (int i = 0; i < 4; i++) {
        int k = kb + threadIdx.y + i * 8;
        int n = nb + threadIdx.x;
        tile[threadIdx.y + i * 8][threadIdx.x] =
            W[((size_t)l * F_DIM + k) * F_DIM + n] * adj[(size_t)k * F_DIM + n];
    }
    __syncthreads();
    #pragma unroll
    for (int i = 0; i < 4; i++) {
        int n = nb + threadIdx.y + i * 8;
        int k = kb + threadIdx.x;
        float v = tile[threadIdx.x][threadIdx.y + i * 8];
        __half h = __float2half(v);
        float rem = v - __half2float(h);
        size_t o = ((size_t)l * F_DIM + n) * F_DIM + k;
        g_Bh[o] = h;
        g_Bl[o] = __float2half(rem);
    }
}

// ---------------- x -> fp16 (two launches so ncu -s 5 lands on layer-1 gemm) ----
__global__ void tohalf_kernel(const float* __restrict__ X, size_t off4) {
    size_t idx = off4 + (size_t)blockIdx.x * blockDim.x + threadIdx.x;
    float4 v = ((const float4*)X)[idx];
    __half2 p0{__float2half(v.x), __float2half(v.y)};
    __half2 p1{__float2half(v.z), __float2half(v.w)};
    uint2 u;
    u.x = *(uint32_t*)&p0; u.y = *(uint32_t*)&p1;
    ((uint2*)g_A)[idx] = u;
}

// ---------------- GEMM: Y = relu(A @ (Bh+Bl) + bias) + Hres ----------------
// 8 warps, warp tile 64x32 (2 warps M x 4 warps N), 2 CTAs/SM.
__global__ void __launch_bounds__(THREADS, 2)
gemm_mma_kernel(const __half* __restrict__ A, const float* __restrict__ Hres,
                const __half* __restrict__ Bh, const __half* __restrict__ Bl,
                const float* __restrict__ bias, float* __restrict__ Y)
{
    extern __shared__ char smem[];
    const uint32_t sb = smem_u32(smem);
    const int tid = threadIdx.x;
    const int wid = tid >> 5;
    const int lid = tid & 31;
    const int warpM = wid & 1;     // 2 warps in M, tile 64 rows
    const int warpN = wid >> 1;    // 4 warps in N, tile 32 cols
    const int blockRow = blockIdx.y * BM;
    const int blockCol = blockIdx.x * BN;

    const char* gA  = (const char*)(A  + (size_t)blockRow * F_DIM);
    const char* gBh = (const char*)(Bh + (size_t)blockCol * F_DIM);
    const char* gBl = (const char*)(Bl + (size_t)blockCol * F_DIM);

    // per stage: 3 tiles x 512 x 16B chunks; 256 threads -> 2 chunks per tile per thread
    auto load_stage = [&](int c, int s) {
        const int k0b = c * BK * 2;
        const uint32_t base = sb + (uint32_t)s * STAGE_BYTES;
        #pragma unroll
        for (int i = 0; i < 2; i++) {
            const int u = tid + 256 * i;
            const int r = u >> 2;
            const int c16 = u & 3;
            const uint32_t soff = (uint32_t)(r * ROW_BYTES + c16 * 16);
            const size_t goff = (size_t)r * (F_DIM * 2) + k0b + c16 * 16;
            cp_async16(base + A_OFF  + soff, gA  + goff);
            cp_async16(base + BH_OFF + soff, gBh + goff);
            cp_async16(base + BL_OFF + soff, gBl + goff);
        }
    };

    float acc[4][4][4];   // mt(4 x 16 rows) x nt(4 x 8 cols) x 4
    #pragma unroll
    for (int mt = 0; mt < 4; mt++)
        #pragma unroll
        for (int nt = 0; nt < 4; nt++)
            #pragma unroll
            for (int i = 0; i < 4; i++) acc[mt][nt][i] = 0.f;

    load_stage(0, 0); CP_COMMIT();
    load_stage(1, 1); CP_COMMIT();

    const uint32_t aRowOff = (uint32_t)((warpM * 64 + (lid & 15)) * ROW_BYTES + ((lid >> 4) << 4));
    const uint32_t bRowOff = (uint32_t)((warpN * 32 + (lid & 15)) * ROW_BYTES + ((lid >> 4) << 4));

    for (int c = 0; c < NCHUNK; ++c) {
        CP_WAIT(1);
        __syncthreads();
        if (c + 2 < NCHUNK) load_stage(c + 2, (c + 2) % STAGES);
        CP_COMMIT();

        const uint32_t stage = sb + (uint32_t)(c % STAGES) * STAGE_BYTES;
        #pragma unroll
        for (int kh = 0; kh < 2; kh++) {
            const uint32_t kb = (uint32_t)(kh * 32);  // 16 fp16 = 32B
            uint32_t a[4][4], bh[2][4], bl[2][4];
            #pragma unroll
            for (int mt = 0; mt < 4; mt++)
                LDSM_X4(a[mt], stage + A_OFF + aRowOff + (uint32_t)(mt * 16 * ROW_BYTES) + kb);
            #pragma unroll
            for (int g = 0; g < 2; g++) {
                LDSM_X4(bh[g], stage + BH_OFF + bRowOff + (uint32_t)(g * 16 * ROW_BYTES) + kb);
                LDSM_X4(bl[g], stage + BL_OFF + bRowOff + (uint32_t)(g * 16 * ROW_BYTES) + kb);
            }
            #pragma unroll
            for (int mt = 0; mt < 4; mt++)
                #pragma unroll
                for (int nt = 0; nt < 4; nt++) {
                    const int g = nt >> 1, h = nt & 1;
                    mma_f32acc(acc[mt][nt], a[mt], bh[g][h], bh[g][h + 2]);
                }
            #pragma unroll
            for (int mt = 0; mt < 4; mt++)
                #pragma unroll
                for (int nt = 0; nt < 4; nt++) {
                    const int g = nt >> 1, h = nt & 1;
                    mma_f32acc(acc[mt][nt], a[mt], bl[g][h], bl[g][h + 2]);
                }
        }
    }

    // ---- epilogue: bias + relu + residual ----
    const int lane4 = lid >> 2;
    const int lanec = (lid & 3) * 2;
    float2 bv[4];
    #pragma unroll
    for (int nt = 0; nt < 4; nt++)
        bv[nt] = *(const float2*)(bias + blockCol + warpN * 32 + nt * 8 + lanec);

    #pragma unroll
    for (int mt = 0; mt < 4; mt++) {
        const int r0 = blockRow + warpM * 64 + mt * 16 + lane4;
        const int r1 = r0 + 8;
        #pragma unroll
        for (int nt = 0; nt < 4; nt++) {
            const int col = blockCol + warpN * 32 + nt * 8 + lanec;
            const size_t o0 = (size_t)r0 * F_DIM + col;
            const size_t o1 = (size_t)r1 * F_DIM + col;
            float2 h0 = *(const float2*)(Hres + o0);
            float2 h1 = *(const float2*)(Hres + o1);
            float* a4 = acc[mt][nt];
            float2 y0, y1;
            y0.x = fmaxf(a4[0] + bv[nt].x, 0.f) + h0.x;
            y0.y = fmaxf(a4[1] + bv[nt].y, 0.f) + h0.y;
            y1.x = fmaxf(a4[2] + bv[nt].x, 0.f) + h1.x;
            y1.y = fmaxf(a4[3] + bv[nt].y, 0.f) + h1.y;
            *(float2*)(Y + o0) = y0;
            *(float2*)(Y + o1) = y1;
        }
    }
}

// ---------------- LayerNorm (+ optional fp16 store for next layer's A) ----------------
__global__ void ln_split_kernel(const float* __restrict__ Yin, float* __restrict__ Yout,
                                int do_half) {
    const int row = blockIdx.x;
    const size_t base4 = (size_t)row * (F_DIM / 4);
    float4 v = ((const float4*)Yin)[base4 + threadIdx.x];
    float s  = v.x + v.y + v.z + v.w;
    float ss = v.x * v.x + v.y * v.y + v.z * v.z + v.w * v.w;
    #pragma unroll
    for (int o = 16; o > 0; o >>= 1) {
        s  += __shfl_down_sync(0xffffffffu, s,  o);
        ss += __shfl_down_sync(0xffffffffu, ss, o);
    }
    __shared__ float sh_s[8], sh_ss[8];
    const int warp = threadIdx.x >> 5, lane = threadIdx.x & 31;
    if (lane == 0) { sh_s[warp] = s; sh_ss[warp] = ss; }
    __syncthreads();
    float st = 0.f, sst = 0.f;
    #pragma unroll
    for (int w = 0; w < 8; w++) { st += sh_s[w]; sst += sh_ss[w]; }
    const float inv = 1.0f / (float)F_DIM;
    const float mu  = st * inv;
    const float var = sst * inv - mu * mu;
    const float r   = rsqrtf(var + 1e-5f);
    v.x = (v.x - mu) * r; v.y = (v.y - mu) * r;
    v.z = (v.z - mu) * r; v.w = (v.w - mu) * r;
    ((float4*)Yout)[base4 + threadIdx.x] = v;
    if (do_half) {
        __half2 p0{__float2half(v.x), __float2half(v.y)};
        __half2 p1{__float2half(v.z), __float2half(v.w)};
        uint2 u;
        u.x = *(uint32_t*)&p0; u.y = *(uint32_t*)&p1;
        ((uint2*)g_A)[base4 + threadIdx.x] = u;
    }
}

// ---------------- launch ----------------
extern "C" void kernel_launch(void* const* d_in, const int* in_sizes, int n_in,
                              void* d_out, int out_size) {
    const float* x    = (const float*)d_in[0];   // (16384, 1024)
    const float* adj  = (const float*)d_in[1];   // (1024, 1024)
    const float* W    = (const float*)d_in[2];   // (5, 1024, 1024)
    const float* bias = (const float*)d_in[3];   // (5, 1024)
    float* out = (float*)d_out;

    cudaFuncSetAttribute(gemm_mma_kernel,
                         cudaFuncAttributeMaxDynamicSharedMemorySize, SMEM_TOTAL);

    __half *bh, *bl, *ah;
    float *bufA, *bufB;
    cudaGetSymbolAddress((void**)&bh,   g_Bh);
    cudaGetSymbolAddress((void**)&bl,   g_Bl);
    cudaGetSymbolAddress((void**)&ah,   g_A);
    cudaGetSymbolAddress((void**)&bufA, g_bufA);
    cudaGetSymbolAddress((void**)&bufB, g_bufB);

    prep_kernel<<<dim3(F_DIM / 32, F_DIM / 32, L_LAYERS), dim3(32, 8)>>>(W, adj);
    const size_t half4 = (size_t)M_ROWS * F_DIM / 4 / 2;
    tohalf_kernel<<<(int)(half4 / 256), 256>>>(x, 0);
    tohalf_kernel<<<(int)(half4 / 256), 256>>>(x, half4);

    const float* h = x;
    for (int l = 0; l < L_LAYERS; ++l) {
        const size_t bo = (size_t)l * F_DIM * F_DIM;
        gemm_mma_kernel<<<dim3(F_DIM / BN, M_ROWS / BM), THREADS, SMEM_TOTAL>>>(
            ah, h, bh + bo, bl + bo, bias + (size_t)l * F_DIM, bufA);
        const int last = (l == L_LAYERS - 1);
        ln_split_kernel<<<M_ROWS, 256>>>(bufA, last ? out : bufB, !last);
        h = bufB;
    }
}

// round 11
// speedup vs baseline: 1.0881x; 1.0532x over previous
#include <cuda_runtime.h>
#include <cuda_fp16.h>
#include <cstdint>

#define M_ROWS   16384
#define F_DIM    1024
#define L_LAYERS 5

#define BM 128
#define BN 128
#define BK 32
#define NCHUNK (F_DIM / BK)   // 32
#define THREADS 512
#define STAGES 4

#define ROW_BYTES   80
#define TILE_BYTES  (128 * ROW_BYTES)       // 10240
#define A_OFF       0u
#define BH_OFF      (1u * TILE_BYTES)
#define BL_OFF      (2u * TILE_BYTES)
#define STAGE_BYTES (3u * TILE_BYTES)       // 30720
#define SMEM_TOTAL  (STAGES * STAGE_BYTES)  // 122880

// ---------------- scratch ----------------
__device__ __half g_Bh[(size_t)L_LAYERS * F_DIM * F_DIM];  // 10 MB
__device__ __half g_Bl[(size_t)L_LAYERS * F_DIM * F_DIM];  // 10 MB
__device__ __half g_A [(size_t)M_ROWS * F_DIM];            // 32 MB  h (fp16): A AND residual
__device__ float g_bufA[(size_t)M_ROWS * F_DIM];           // 64 MB  ypre

// ---------------- helpers ----------------
__device__ __forceinline__ uint32_t smem_u32(const void* p) {
    uint32_t a;
    asm("{ .reg .u64 t; cvta.to.shared.u64 t, %1; cvt.u32.u64 %0, t; }" : "=r"(a) : "l"(p));
    return a;
}
__device__ __forceinline__ void cp_async16(uint32_t dst, const void* src) {
    asm volatile("cp.async.cg.shared.global [%0], [%1], 16;" :: "r"(dst), "l"(src));
}
#define CP_COMMIT()  asm volatile("cp.async.commit_group;")
#define CP_WAIT(n)   asm volatile("cp.async.wait_group %0;" :: "n"(n))

#define LDSM_X4(r, addr) \
    asm volatile("ldmatrix.sync.aligned.m8n8.x4.shared.b16 {%0,%1,%2,%3}, [%4];" \
        : "=r"((r)[0]), "=r"((r)[1]), "=r"((r)[2]), "=r"((r)[3]) : "r"(addr))

__device__ __forceinline__ void mma_f32acc(float* d, const uint32_t* a,
                                           uint32_t b0, uint32_t b1) {
    asm volatile(
        "mma.sync.aligned.m16n8k16.row.col.f32.f16.f16.f32 "
        "{%0,%1,%2,%3}, {%4,%5,%6,%7}, {%8,%9}, {%0,%1,%2,%3};"
        : "+f"(d[0]), "+f"(d[1]), "+f"(d[2]), "+f"(d[3])
        : "r"(a[0]), "r"(a[1]), "r"(a[2]), "r"(a[3]), "r"(b0), "r"(b1));
}
__device__ __forceinline__ void mma_f16acc(uint32_t* d, const uint32_t* a,
                                           uint32_t b0, uint32_t b1) {
    asm volatile(
        "mma.sync.aligned.m16n8k16.row.col.f16.f16.f16.f16 "
        "{%0,%1}, {%2,%3,%4,%5}, {%6,%7}, {%0,%1};"
        : "+r"(d[0]), "+r"(d[1])
        : "r"(a[0]), "r"(a[1]), "r"(a[2]), "r"(a[3]), "r"(b0), "r"(b1));
}

// ---------------- prep: B{h,l}[l][n][k] = split_fp16(W[l][k][n] * adj[k][n]) ----------------
__global__ void prep_kernel(const float* __restrict__ W, const float* __restrict__ adj) {
    __shared__ float tile[32][33];
    const int l = blockIdx.z;
    const int kb = blockIdx.x * 32;
    const int nb = blockIdx.y * 32;
    #pragma unroll
    for (int i = 0; i < 4; i++) {
        int k = kb + threadIdx.y + i * 8;
        int n = nb + threadIdx.x;
        tile[threadIdx.y + i * 8][threadIdx.x] =
            W[((size_t)l * F_DIM + k) * F_DIM + n] * adj[(size_t)k * F_DIM + n];
    }
    __syncthreads();
    #pragma unroll
    for (int i = 0; i < 4; i++) {
        int n = nb + threadIdx.y + i * 8;
        int k = kb + threadIdx.x;
        float v = tile[threadIdx.x][threadIdx.y + i * 8];
        __half h = __float2half(v);
        float rem = v - __half2float(h);
        size_t o = ((size_t)l * F_DIM + n) * F_DIM + k;
        g_Bh[o] = h;
        g_Bl[o] = __float2half(rem);
    }
}

// ---------------- x -> fp16 (two launches so ncu -s 5 lands on layer-1 gemm) ----
__global__ void tohalf_kernel(const float* __restrict__ X, size_t off4) {
    size_t idx = off4 + (size_t)blockIdx.x * blockDim.x + threadIdx.x;
    float4 v = ((const float4*)X)[idx];
    __half2 p0{__float2half(v.x), __float2half(v.y)};
    __half2 p1{__float2half(v.z), __float2half(v.w)};
    uint2 u;
    u.x = *(uint32_t*)&p0; u.y = *(uint32_t*)&p1;
    ((uint2*)g_A)[idx] = u;
}

// ---------------- GEMM: ypre = relu(A @ (Bh+Bl) + bias) + A   (A fp16, residual fp16) ----
__global__ void __launch_bounds__(THREADS, 1)
gemm_mma_kernel(const __half* __restrict__ A,
                const __half* __restrict__ Bh, const __half* __restrict__ Bl,
                const float* __restrict__ bias, float* __restrict__ Y)
{
    extern __shared__ char smem[];
    const uint32_t sb = smem_u32(smem);
    const int tid = threadIdx.x;
    const int wid = tid >> 5;
    const int lid = tid & 31;
    const int warpM = wid & 3;     // 4 warps in M, tile 32 rows
    const int warpN = wid >> 2;    // 4 warps in N, tile 32 cols
    const int blockRow = blockIdx.y * BM;
    const int blockCol = blockIdx.x * BN;

    const char* gA  = (const char*)(A  + (size_t)blockRow * F_DIM);
    const char* gBh = (const char*)(Bh + (size_t)blockCol * F_DIM);
    const char* gBl = (const char*)(Bl + (size_t)blockCol * F_DIM);

    auto load_stage = [&](int c, int s) {
        const int k0b = c * BK * 2;
        const uint32_t base = sb + (uint32_t)s * STAGE_BYTES;
        const int r = tid >> 2;
        const int c16 = tid & 3;
        const uint32_t soff = (uint32_t)(r * ROW_BYTES + c16 * 16);
        const size_t goff = (size_t)r * (F_DIM * 2) + k0b + c16 * 16;
        cp_async16(base + A_OFF  + soff, gA  + goff);
        cp_async16(base + BH_OFF + soff, gBh + goff);
        cp_async16(base + BL_OFF + soff, gBl + goff);
    };

    float    acc [2][4][4];   // fp32 acc for A@Bh
    uint32_t acch[2][4][2];   // fp16 acc for A@Bl (correction, |vals| ~2^-11)
    #pragma unroll
    for (int mt = 0; mt < 2; mt++)
        #pragma unroll
        for (int nt = 0; nt < 4; nt++) {
            #pragma unroll
            for (int i = 0; i < 4; i++) acc[mt][nt][i] = 0.f;
            acch[mt][nt][0] = 0u; acch[mt][nt][1] = 0u;
        }

    load_stage(0, 0); CP_COMMIT();
    load_stage(1, 1); CP_COMMIT();
    load_stage(2, 2); CP_COMMIT();

    const uint32_t aRowOff = (uint32_t)((warpM * 32 + (lid & 15)) * ROW_BYTES + ((lid >> 4) << 4));
    const uint32_t bRowOff = (uint32_t)((warpN * 32 + (lid & 15)) * ROW_BYTES + ((lid >> 4) << 4));

    for (int c = 0; c < NCHUNK; ++c) {
        CP_WAIT(2);
        __syncthreads();
        if (c + 3 < NCHUNK) load_stage(c + 3, (c + 3) & 3);
        CP_COMMIT();

        const uint32_t stage = sb + (uint32_t)(c & 3) * STAGE_BYTES;
        #pragma unroll
        for (int kh = 0; kh < 2; kh++) {
            const uint32_t kb = (uint32_t)(kh * 32);
            uint32_t a[2][4], bh[2][4], bl[2][4];
            #pragma unroll
            for (int mt = 0; mt < 2; mt++)
                LDSM_X4(a[mt], stage + A_OFF + aRowOff + (uint32_t)(mt * 16 * ROW_BYTES) + kb);
            #pragma unroll
            for (int g = 0; g < 2; g++) {
                LDSM_X4(bh[g], stage + BH_OFF + bRowOff + (uint32_t)(g * 16 * ROW_BYTES) + kb);
                LDSM_X4(bl[g], stage + BL_OFF + bRowOff + (uint32_t)(g * 16 * ROW_BYTES) + kb);
            }
            #pragma unroll
            for (int mt = 0; mt < 2; mt++)
                #pragma unroll
                for (int nt = 0; nt < 4; nt++) {
                    const int g = nt >> 1, h = nt & 1;
                    mma_f32acc(acc[mt][nt], a[mt], bh[g][h], bh[g][h + 2]);
                }
            #pragma unroll
            for (int mt = 0; mt < 2; mt++)
                #pragma unroll
                for (int nt = 0; nt < 4; nt++) {
                    const int g = nt >> 1, h = nt & 1;
                    mma_f16acc(acch[mt][nt], a[mt], bl[g][h], bl[g][h + 2]);
                }
        }
    }

    // ---- epilogue: merge lo acc, bias + relu + residual (residual fp16 from A) ----
    const int lane4 = lid >> 2;
    const int lanec = (lid & 3) * 2;
    float2 bv[4];
    #pragma unroll
    for (int nt = 0; nt < 4; nt++)
        bv[nt] = *(const float2*)(bias + blockCol + warpN * 32 + nt * 8 + lanec);

    #pragma unroll
    for (int mt = 0; mt < 2; mt++) {
        const int r0 = blockRow + warpM * 32 + mt * 16 + lane4;
        const int r1 = r0 + 8;
        #pragma unroll
        for (int nt = 0; nt < 4; nt++) {
            const int col = blockCol + warpN * 32 + nt * 8 + lanec;
            const size_t o0 = (size_t)r0 * F_DIM + col;
            const size_t o1 = (size_t)r1 * F_DIM + col;
            float2 h0 = __half22float2(*(const __half2*)(A + o0));
            float2 h1 = __half22float2(*(const __half2*)(A + o1));
            float* a4 = acc[mt][nt];
            __half2 c0 = *(__half2*)&acch[mt][nt][0];
            __half2 c1 = *(__half2*)&acch[mt][nt][1];
            float s0 = a4[0] + __low2float(c0);
            float s1 = a4[1] + __high2float(c0);
            float s2 = a4[2] + __low2float(c1);
            float s3 = a4[3] + __high2float(c1);
            float2 y0, y1;
            y0.x = fmaxf(s0 + bv[nt].x, 0.f) + h0.x;
            y0.y = fmaxf(s1 + bv[nt].y, 0.f) + h0.y;
            y1.x = fmaxf(s2 + bv[nt].x, 0.f) + h1.x;
            y1.y = fmaxf(s3 + bv[nt].y, 0.f) + h1.y;
            *(float2*)(Y + o0) = y0;
            *(float2*)(Y + o1) = y1;
        }
    }
}

// ---------------- LayerNorm: intermediate -> fp16 g_A only; last -> fp32 out ----------------
__global__ void ln_kernel(const float* __restrict__ Yin, float* __restrict__ OutF32,
                          int last) {
    const int row = blockIdx.x;
    const size_t base4 = (size_t)row * (F_DIM / 4);
    float4 v = ((const float4*)Yin)[base4 + threadIdx.x];
    float s  = v.x + v.y + v.z + v.w;
    float ss = v.x * v.x + v.y * v.y + v.z * v.z + v.w * v.w;
    #pragma unroll
    for (int o = 16; o > 0; o >>= 1) {
        s  += __shfl_down_sync(0xffffffffu, s,  o);
        ss += __shfl_down_sync(0xffffffffu, ss, o);
    }
    __shared__ float sh_s[8], sh_ss[8];
    const int warp = threadIdx.x >> 5, lane = threadIdx.x & 31;
    if (lane == 0) { sh_s[warp] = s; sh_ss[warp] = ss; }
    __syncthreads();
    float st = 0.f, sst = 0.f;
    #pragma unroll
    for (int w = 0; w < 8; w++) { st += sh_s[w]; sst += sh_ss[w]; }
    const float inv = 1.0f / (float)F_DIM;
    const float mu  = st * inv;
    const float var = sst * inv - mu * mu;
    const float r   = rsqrtf(var + 1e-5f);
    v.x = (v.x - mu) * r; v.y = (v.y - mu) * r;
    v.z = (v.z - mu) * r; v.w = (v.w - mu) * r;
    if (last) {
        ((float4*)OutF32)[base4 + threadIdx.x] = v;
    } else {
        __half2 p0{__float2half(v.x), __float2half(v.y)};
        __half2 p1{__float2half(v.z), __float2half(v.w)};
        uint2 u;
        u.x = *(uint32_t*)&p0; u.y = *(uint32_t*)&p1;
        ((uint2*)g_A)[base4 + threadIdx.x] = u;
    }
}

// ---------------- launch ----------------
extern "C" void kernel_launch(void* const* d_in, const int* in_sizes, int n_in,
                              void* d_out, int out_size) {
    const float* x    = (const float*)d_in[0];   // (16384, 1024)
    const float* adj  = (const float*)d_in[1];   // (1024, 1024)
    const float* W    = (const float*)d_in[2];   // (5, 1024, 1024)
    const float* bias = (const float*)d_in[3];   // (5, 1024)
    float* out = (float*)d_out;

    cudaFuncSetAttribute(gemm_mma_kernel,
                         cudaFuncAttributeMaxDynamicSharedMemorySize, SMEM_TOTAL);

    __half *bh, *bl, *ah;
    float *bufA;
    cudaGetSymbolAddress((void**)&bh,   g_Bh);
    cudaGetSymbolAddress((void**)&bl,   g_Bl);
    cudaGetSymbolAddress((void**)&ah,   g_A);
    cudaGetSymbolAddress((void**)&bufA, g_bufA);

    prep_kernel<<<dim3(F_DIM / 32, F_DIM / 32, L_LAYERS), dim3(32, 8)>>>(W, adj);
    const size_t half4 = (size_t)M_ROWS * F_DIM / 4 / 2;
    tohalf_kernel<<<(int)(half4 / 256), 256>>>(x, 0);
    tohalf_kernel<<<(int)(half4 / 256), 256>>>(x, half4);

    for (int l = 0; l < L_LAYERS; ++l) {
        const size_t bo = (size_t)l * F_DIM * F_DIM;
        gemm_mma_kernel<<<dim3(F_DIM / BN, M_ROWS / BM), THREADS, SMEM_TOTAL>>>(
            ah, bh + bo, bl + bo, bias + (size_t)l * F_DIM, bufA);
        const int last = (l == L_LAYERS - 1);
        ln_kernel<<<M_ROWS, 256>>>(bufA, last ? out : nullptr, last);
    }
}

// round 12
// speedup vs baseline: 1.1234x; 1.0324x over previous
#include <cuda_runtime.h>
#include <cuda_fp16.h>
#include <cstdint>

#define M_ROWS   16384
#define F_DIM    1024
#define L_LAYERS 5
#define M_HALF   (M_ROWS / 2)

#define BM 128
#define BN 128
#define BK 32
#define NCHUNK (F_DIM / BK)   // 32
#define THREADS 512
#define STAGES 4

#define ROW_BYTES   80
#define TILE_BYTES  (128 * ROW_BYTES)       // 10240
#define A_OFF       0u
#define BH_OFF      (1u * TILE_BYTES)
#define BL_OFF      (2u * TILE_BYTES)
#define STAGE_BYTES (3u * TILE_BYTES)       // 30720
#define SMEM_TOTAL  (STAGES * STAGE_BYTES)  // 122880

// ---------------- scratch ----------------
__device__ __half g_Bh[(size_t)L_LAYERS * F_DIM * F_DIM];  // 10 MB
__device__ __half g_Bl[(size_t)L_LAYERS * F_DIM * F_DIM];  // 10 MB
__device__ __half g_A [(size_t)M_ROWS * F_DIM];            // 32 MB  h (fp16): A AND residual
__device__ float g_bufA[(size_t)M_ROWS * F_DIM];           // 64 MB  ypre

// ---------------- helpers ----------------
__device__ __forceinline__ uint32_t smem_u32(const void* p) {
    uint32_t a;
    asm("{ .reg .u64 t; cvta.to.shared.u64 t, %1; cvt.u32.u64 %0, t; }" : "=r"(a) : "l"(p));
    return a;
}
__device__ __forceinline__ void cp_async16(uint32_t dst, const void* src) {
    asm volatile("cp.async.cg.shared.global [%0], [%1], 16;" :: "r"(dst), "l"(src));
}
#define CP_COMMIT()  asm volatile("cp.async.commit_group;")
#define CP_WAIT(n)   asm volatile("cp.async.wait_group %0;" :: "n"(n))

#define LDSM_X4(r, addr) \
    asm volatile("ldmatrix.sync.aligned.m8n8.x4.shared.b16 {%0,%1,%2,%3}, [%4];" \
        : "=r"((r)[0]), "=r"((r)[1]), "=r"((r)[2]), "=r"((r)[3]) : "r"(addr))

__device__ __forceinline__ void mma_f32acc(float* d, const uint32_t* a,
                                           uint32_t b0, uint32_t b1) {
    asm volatile(
        "mma.sync.aligned.m16n8k16.row.col.f32.f16.f16.f32 "
        "{%0,%1,%2,%3}, {%4,%5,%6,%7}, {%8,%9}, {%0,%1,%2,%3};"
        : "+f"(d[0]), "+f"(d[1]), "+f"(d[2]), "+f"(d[3])
        : "r"(a[0]), "r"(a[1]), "r"(a[2]), "r"(a[3]), "r"(b0), "r"(b1));
}
__device__ __forceinline__ void mma_f16acc(uint32_t* d, const uint32_t* a,
                                           uint32_t b0, uint32_t b1) {
    asm volatile(
        "mma.sync.aligned.m16n8k16.row.col.f16.f16.f16.f16 "
        "{%0,%1}, {%2,%3,%4,%5}, {%6,%7}, {%0,%1};"
        : "+r"(d[0]), "+r"(d[1])
        : "r"(a[0]), "r"(a[1]), "r"(a[2]), "r"(a[3]), "r"(b0), "r"(b1));
}

// ---------------- prep: B{h,l}[l][n][k] = split_fp16(W[l][k][n] * adj[k][n]) ----------------
__global__ void prep_kernel(const float* __restrict__ W, const float* __restrict__ adj) {
    __shared__ float tile[32][33];
    const int l = blockIdx.z;
    const int kb = blockIdx.x * 32;
    const int nb = blockIdx.y * 32;
    #pragma unroll
    for (int i = 0; i < 4; i++) {
        int k = kb + threadIdx.y + i * 8;
        int n = nb + threadIdx.x;
        tile[threadIdx.y + i * 8][threadIdx.x] =
            W[((size_t)l * F_DIM + k) * F_DIM + n] * adj[(size_t)k * F_DIM + n];
    }
    __syncthreads();
    #pragma unroll
    for (int i = 0; i < 4; i++) {
        int n = nb + threadIdx.y + i * 8;
        int k = kb + threadIdx.x;
        float v = tile[threadIdx.x][threadIdx.y + i * 8];
        __half h = __float2half(v);
        float rem = v - __half2float(h);
        size_t o = ((size_t)l * F_DIM + n) * F_DIM + k;
        g_Bh[o] = h;
        g_Bl[o] = __float2half(rem);
    }
}

// ---------------- x -> fp16 ----------------
__global__ void tohalf_kernel(const float* __restrict__ X, size_t off4) {
    size_t idx = off4 + (size_t)blockIdx.x * blockDim.x + threadIdx.x;
    float4 v = ((const float4*)X)[idx];
    __half2 p0{__float2half(v.x), __float2half(v.y)};
    __half2 p1{__float2half(v.z), __float2half(v.w)};
    uint2 u;
    u.x = *(uint32_t*)&p0; u.y = *(uint32_t*)&p1;
    ((uint2*)g_A)[idx] = u;
}

// ---------------- GEMM: ypre = relu(A @ (Bh+Bl) + bias) + A   (A fp16; row-local) ----
__global__ void __launch_bounds__(THREADS, 1)
gemm_mma_kernel(const __half* __restrict__ A,
                const __half* __restrict__ Bh, const __half* __restrict__ Bl,
                const float* __restrict__ bias, float* __restrict__ Y)
{
    extern __shared__ char smem[];
    const uint32_t sb = smem_u32(smem);
    const int tid = threadIdx.x;
    const int wid = tid >> 5;
    const int lid = tid & 31;
    const int warpM = wid & 3;     // 4 warps in M, tile 32 rows
    const int warpN = wid >> 2;    // 4 warps in N, tile 32 cols
    const int blockRow = blockIdx.y * BM;
    const int blockCol = blockIdx.x * BN;

    const char* gA  = (const char*)(A  + (size_t)blockRow * F_DIM);
    const char* gBh = (const char*)(Bh + (size_t)blockCol * F_DIM);
    const char* gBl = (const char*)(Bl + (size_t)blockCol * F_DIM);

    auto load_stage = [&](int c, int s) {
        const int k0b = c * BK * 2;
        const uint32_t base = sb + (uint32_t)s * STAGE_BYTES;
        const int r = tid >> 2;
        const int c16 = tid & 3;
        const uint32_t soff = (uint32_t)(r * ROW_BYTES + c16 * 16);
        const size_t goff = (size_t)r * (F_DIM * 2) + k0b + c16 * 16;
        cp_async16(base + A_OFF  + soff, gA  + goff);
        cp_async16(base + BH_OFF + soff, gBh + goff);
        cp_async16(base + BL_OFF + soff, gBl + goff);
    };

    float    acc [2][4][4];
    uint32_t acch[2][4][2];
    #pragma unroll
    for (int mt = 0; mt < 2; mt++)
        #pragma unroll
        for (int nt = 0; nt < 4; nt++) {
            #pragma unroll
            for (int i = 0; i < 4; i++) acc[mt][nt][i] = 0.f;
            acch[mt][nt][0] = 0u; acch[mt][nt][1] = 0u;
        }

    load_stage(0, 0); CP_COMMIT();
    load_stage(1, 1); CP_COMMIT();
    load_stage(2, 2); CP_COMMIT();

    const uint32_t aRowOff = (uint32_t)((warpM * 32 + (lid & 15)) * ROW_BYTES + ((lid >> 4) << 4));
    const uint32_t bRowOff = (uint32_t)((warpN * 32 + (lid & 15)) * ROW_BYTES + ((lid >> 4) << 4));

    for (int c = 0; c < NCHUNK; ++c) {
        CP_WAIT(2);
        __syncthreads();
        if (c + 3 < NCHUNK) load_stage(c + 3, (c + 3) & 3);
        CP_COMMIT();

        const uint32_t stage = sb + (uint32_t)(c & 3) * STAGE_BYTES;
        #pragma unroll
        for (int kh = 0; kh < 2; kh++) {
            const uint32_t kb = (uint32_t)(kh * 32);
            uint32_t a[2][4], bh[2][4], bl[2][4];
            #pragma unroll
            for (int mt = 0; mt < 2; mt++)
                LDSM_X4(a[mt], stage + A_OFF + aRowOff + (uint32_t)(mt * 16 * ROW_BYTES) + kb);
            #pragma unroll
            for (int g = 0; g < 2; g++) {
                LDSM_X4(bh[g], stage + BH_OFF + bRowOff + (uint32_t)(g * 16 * ROW_BYTES) + kb);
                LDSM_X4(bl[g], stage + BL_OFF + bRowOff + (uint32_t)(g * 16 * ROW_BYTES) + kb);
            }
            #pragma unroll
            for (int mt = 0; mt < 2; mt++)
                #pragma unroll
                for (int nt = 0; nt < 4; nt++) {
                    const int g = nt >> 1, h = nt & 1;
                    mma_f32acc(acc[mt][nt], a[mt], bh[g][h], bh[g][h + 2]);
                }
            #pragma unroll
            for (int mt = 0; mt < 2; mt++)
                #pragma unroll
                for (int nt = 0; nt < 4; nt++) {
                    const int g = nt >> 1, h = nt & 1;
                    mma_f16acc(acch[mt][nt], a[mt], bl[g][h], bl[g][h + 2]);
                }
        }
    }

    // ---- epilogue: merge lo acc, bias + relu + residual (fp16 residual from A) ----
    const int lane4 = lid >> 2;
    const int lanec = (lid & 3) * 2;
    float2 bv[4];
    #pragma unroll
    for (int nt = 0; nt < 4; nt++)
        bv[nt] = *(const float2*)(bias + blockCol + warpN * 32 + nt * 8 + lanec);

    #pragma unroll
    for (int mt = 0; mt < 2; mt++) {
        const int r0 = blockRow + warpM * 32 + mt * 16 + lane4;
        const int r1 = r0 + 8;
        #pragma unroll
        for (int nt = 0; nt < 4; nt++) {
            const int col = blockCol + warpN * 32 + nt * 8 + lanec;
            const size_t o0 = (size_t)r0 * F_DIM + col;
            const size_t o1 = (size_t)r1 * F_DIM + col;
            float2 h0 = __half22float2(*(const __half2*)(A + o0));
            float2 h1 = __half22float2(*(const __half2*)(A + o1));
            float* a4 = acc[mt][nt];
            __half2 c0 = *(__half2*)&acch[mt][nt][0];
            __half2 c1 = *(__half2*)&acch[mt][nt][1];
            float s0 = a4[0] + __low2float(c0);
            float s1 = a4[1] + __high2float(c0);
            float s2 = a4[2] + __low2float(c1);
            float s3 = a4[3] + __high2float(c1);
            float2 y0, y1;
            y0.x = fmaxf(s0 + bv[nt].x, 0.f) + h0.x;
            y0.y = fmaxf(s1 + bv[nt].y, 0.f) + h0.y;
            y1.x = fmaxf(s2 + bv[nt].x, 0.f) + h1.x;
            y1.y = fmaxf(s3 + bv[nt].y, 0.f) + h1.y;
            *(float2*)(Y + o0) = y0;
            *(float2*)(Y + o1) = y1;
        }
    }
}

// ---------------- LayerNorm: pointer-parameterized for half-pipelines ----------------
__global__ void ln_kernel(const float* __restrict__ Yin, float* __restrict__ OutF32,
                          __half* __restrict__ OutH, int last) {
    const int row = blockIdx.x;
    const size_t base4 = (size_t)row * (F_DIM / 4);
    float4 v = ((const float4*)Yin)[base4 + threadIdx.x];
    float s  = v.x + v.y + v.z + v.w;
    float ss = v.x * v.x + v.y * v.y + v.z * v.z + v.w * v.w;
    #pragma unroll
    for (int o = 16; o > 0; o >>= 1) {
        s  += __shfl_down_sync(0xffffffffu, s,  o);
        ss += __shfl_down_sync(0xffffffffu, ss, o);
    }
    __shared__ float sh_s[8], sh_ss[8];
    const int warp = threadIdx.x >> 5, lane = threadIdx.x & 31;
    if (lane == 0) { sh_s[warp] = s; sh_ss[warp] = ss; }
    __syncthreads();
    float st = 0.f, sst = 0.f;
    #pragma unroll
    for (int w = 0; w < 8; w++) { st += sh_s[w]; sst += sh_ss[w]; }
    const float inv = 1.0f / (float)F_DIM;
    const float mu  = st * inv;
    const float var = sst * inv - mu * mu;
    const float r   = rsqrtf(var + 1e-5f);
    v.x = (v.x - mu) * r; v.y = (v.y - mu) * r;
    v.z = (v.z - mu) * r; v.w = (v.w - mu) * r;
    if (last) {
        ((float4*)OutF32)[base4 + threadIdx.x] = v;
    } else {
        __half2 p0{__float2half(v.x), __float2half(v.y)};
        __half2 p1{__float2half(v.z), __float2half(v.w)};
        uint2 u;
        u.x = *(uint32_t*)&p0; u.y = *(uint32_t*)&p1;
        ((uint2*)OutH)[base4 + threadIdx.x] = u;
    }
}

// ---------------- launch: fork-join dual-stream pipeline over row halves ----------------
extern "C" void kernel_launch(void* const* d_in, const int* in_sizes, int n_in,
                              void* d_out, int out_size) {
    const float* x    = (const float*)d_in[0];   // (16384, 1024)
    const float* adj  = (const float*)d_in[1];   // (1024, 1024)
    const float* W    = (const float*)d_in[2];   // (5, 1024, 1024)
    const float* bias = (const float*)d_in[3];   // (5, 1024)
    float* out = (float*)d_out;

    cudaFuncSetAttribute(gemm_mma_kernel,
                         cudaFuncAttributeMaxDynamicSharedMemorySize, SMEM_TOTAL);

    // Streams/events created once on the first (non-captured correctness) call.
    // Same launch structure is replayed on every call — deterministic work.
    static cudaStream_t s1 = nullptr;
    static cudaEvent_t evFork = nullptr, evJoin = nullptr;
    if (!s1) {
        cudaStreamCreateWithFlags(&s1, cudaStreamNonBlocking);
        cudaEventCreateWithFlags(&evFork, cudaEventDisableTiming);
        cudaEventCreateWithFlags(&evJoin, cudaEventDisableTiming);
    }

    __half *bh, *bl, *ah;
    float *bufA;
    cudaGetSymbolAddress((void**)&bh,   g_Bh);
    cudaGetSymbolAddress((void**)&bl,   g_Bl);
    cudaGetSymbolAddress((void**)&ah,   g_A);
    cudaGetSymbolAddress((void**)&bufA, g_bufA);

    // shared prologue on the capture (default) stream
    prep_kernel<<<dim3(F_DIM / 32, F_DIM / 32, L_LAYERS), dim3(32, 8)>>>(W, adj);
    const size_t half4 = (size_t)M_ROWS * F_DIM / 4 / 2;
    tohalf_kernel<<<(int)(half4 / 256), 256>>>(x, 0);
    tohalf_kernel<<<(int)(half4 / 256), 256>>>(x, half4);

    // fork: bottom-half pipeline runs on s1
    cudaEventRecord(evFork, 0);
    cudaStreamWaitEvent(s1, evFork, 0);

    const size_t roff = (size_t)M_HALF * F_DIM;   // element offset of bottom half
    for (int l = 0; l < L_LAYERS; ++l) {
        const size_t bo = (size_t)l * F_DIM * F_DIM;
        const float* bias_l = bias + (size_t)l * F_DIM;
        const int last = (l == L_LAYERS - 1);
        const dim3 grid(F_DIM / BN, M_HALF / BM);   // (8, 64)

        // top half on default stream
        gemm_mma_kernel<<<grid, THREADS, SMEM_TOTAL>>>(
            ah, bh + bo, bl + bo, bias_l, bufA);
        ln_kernel<<<M_HALF, 256>>>(bufA, last ? out : nullptr, ah, last);

        // bottom half on s1 (fully row-disjoint pipeline)
        gemm_mma_kernel<<<grid, THREADS, SMEM_TOTAL, s1>>>(
            ah + roff, bh + bo, bl + bo, bias_l, bufA + roff);
        ln_kernel<<<M_HALF, 256, 0, s1>>>(bufA + roff,
                                          last ? (out + roff) : nullptr,
                                          ah + roff, last);
    }

    // join
    cudaEventRecord(evJoin, s1);
    cudaStreamWaitEvent(0, evJoin, 0);
}

// round 13
// speedup vs baseline: 1.1482x; 1.0221x over previous
#include <cuda_runtime.h>
#include <cuda_fp16.h>
#include <cstdint>

#define M_ROWS   16384
#define F_DIM    1024
#define L_LAYERS 5
#define NPIPE    4
#define M_QUART  (M_ROWS / NPIPE)   // 4096

#define BM 128
#define BN 128
#define BK 32
#define NCHUNK (F_DIM / BK)   // 32
#define THREADS 512
#define STAGES 4

#define ROW_BYTES   80
#define TILE_BYTES  (128 * ROW_BYTES)       // 10240
#define A_OFF       0u
#define BH_OFF      (1u * TILE_BYTES)
#define BL_OFF      (2u * TILE_BYTES)
#define STAGE_BYTES (3u * TILE_BYTES)       // 30720
#define SMEM_TOTAL  (STAGES * STAGE_BYTES)  // 122880

// ---------------- scratch ----------------
__device__ __half g_Bh[(size_t)L_LAYERS * F_DIM * F_DIM];  // 10 MB
__device__ __half g_Bl[(size_t)L_LAYERS * F_DIM * F_DIM];  // 10 MB
__device__ __half g_A [(size_t)M_ROWS * F_DIM];            // 32 MB  h (fp16): A AND residual
__device__ float g_bufA[(size_t)M_ROWS * F_DIM];           // 64 MB  ypre

// ---------------- helpers ----------------
__device__ __forceinline__ uint32_t smem_u32(const void* p) {
    uint32_t a;
    asm("{ .reg .u64 t; cvta.to.shared.u64 t, %1; cvt.u32.u64 %0, t; }" : "=r"(a) : "l"(p));
    return a;
}
__device__ __forceinline__ void cp_async16(uint32_t dst, const void* src) {
    asm volatile("cp.async.cg.shared.global [%0], [%1], 16;" :: "r"(dst), "l"(src));
}
#define CP_COMMIT()  asm volatile("cp.async.commit_group;")
#define CP_WAIT(n)   asm volatile("cp.async.wait_group %0;" :: "n"(n))

#define LDSM_X4(r, addr) \
    asm volatile("ldmatrix.sync.aligned.m8n8.x4.shared.b16 {%0,%1,%2,%3}, [%4];" \
        : "=r"((r)[0]), "=r"((r)[1]), "=r"((r)[2]), "=r"((r)[3]) : "r"(addr))

__device__ __forceinline__ void mma_f32acc(float* d, const uint32_t* a,
                                           uint32_t b0, uint32_t b1) {
    asm volatile(
        "mma.sync.aligned.m16n8k16.row.col.f32.f16.f16.f32 "
        "{%0,%1,%2,%3}, {%4,%5,%6,%7}, {%8,%9}, {%0,%1,%2,%3};"
        : "+f"(d[0]), "+f"(d[1]), "+f"(d[2]), "+f"(d[3])
        : "r"(a[0]), "r"(a[1]), "r"(a[2]), "r"(a[3]), "r"(b0), "r"(b1));
}
__device__ __forceinline__ void mma_f16acc(uint32_t* d, const uint32_t* a,
                                           uint32_t b0, uint32_t b1) {
    asm volatile(
        "mma.sync.aligned.m16n8k16.row.col.f16.f16.f16.f16 "
        "{%0,%1}, {%2,%3,%4,%5}, {%6,%7}, {%0,%1};"
        : "+r"(d[0]), "+r"(d[1])
        : "r"(a[0]), "r"(a[1]), "r"(a[2]), "r"(a[3]), "r"(b0), "r"(b1));
}

// ---------------- prep: B{h,l}[l][n][k] = split_fp16(W[l][k][n] * adj[k][n]) ----------------
__global__ void prep_kernel(const float* __restrict__ W, const float* __restrict__ adj) {
    __shared__ float tile[32][33];
    const int l = blockIdx.z;
    const int kb = blockIdx.x * 32;
    const int nb = blockIdx.y * 32;
    #pragma unroll
    for (int i = 0; i < 4; i++) {
        int k = kb + threadIdx.y + i * 8;
        int n = nb + threadIdx.x;
        tile[threadIdx.y + i * 8][threadIdx.x] =
            W[((size_t)l * F_DIM + k) * F_DIM + n] * adj[(size_t)k * F_DIM + n];
    }
    __syncthreads();
    #pragma unroll
    for (int i = 0; i < 4; i++) {
        int n = nb + threadIdx.y + i * 8;
        int k = kb + threadIdx.x;
        float v = tile[threadIdx.x][threadIdx.y + i * 8];
        __half h = __float2half(v);
        float rem = v - __half2float(h);
        size_t o = ((size_t)l * F_DIM + n) * F_DIM + k;
        g_Bh[o] = h;
        g_Bl[o] = __float2half(rem);
    }
}

// ---------------- x -> fp16 (per-quarter) ----------------
__global__ void tohalf_kernel(const float* __restrict__ X, size_t off4) {
    size_t idx = off4 + (size_t)blockIdx.x * blockDim.x + threadIdx.x;
    float4 v = ((const float4*)X)[idx];
    __half2 p0{__float2half(v.x), __float2half(v.y)};
    __half2 p1{__float2half(v.z), __float2half(v.w)};
    uint2 u;
    u.x = *(uint32_t*)&p0; u.y = *(uint32_t*)&p1;
    ((uint2*)g_A)[idx] = u;
}

// ---------------- GEMM: ypre = relu(A @ (Bh+Bl) + bias) + A   (A fp16; row-local) ----
__global__ void __launch_bounds__(THREADS, 1)
gemm_mma_kernel(const __half* __restrict__ A,
                const __half* __restrict__ Bh, const __half* __restrict__ Bl,
                const float* __restrict__ bias, float* __restrict__ Y)
{
    extern __shared__ char smem[];
    const uint32_t sb = smem_u32(smem);
    const int tid = threadIdx.x;
    const int wid = tid >> 5;
    const int lid = tid & 31;
    const int warpM = wid & 3;     // 4 warps in M, tile 32 rows
    const int warpN = wid >> 2;    // 4 warps in N, tile 32 cols
    const int blockRow = blockIdx.y * BM;
    const int blockCol = blockIdx.x * BN;

    const char* gA  = (const char*)(A  + (size_t)blockRow * F_DIM);
    const char* gBh = (const char*)(Bh + (size_t)blockCol * F_DIM);
    const char* gBl = (const char*)(Bl + (size_t)blockCol * F_DIM);

    auto load_stage = [&](int c, int s) {
        const int k0b = c * BK * 2;
        const uint32_t base = sb + (uint32_t)s * STAGE_BYTES;
        const int r = tid >> 2;
        const int c16 = tid & 3;
        const uint32_t soff = (uint32_t)(r * ROW_BYTES + c16 * 16);
        const size_t goff = (size_t)r * (F_DIM * 2) + k0b + c16 * 16;
        cp_async16(base + A_OFF  + soff, gA  + goff);
        cp_async16(base + BH_OFF + soff, gBh + goff);
        cp_async16(base + BL_OFF + soff, gBl + goff);
    };

    float    acc [2][4][4];
    uint32_t acch[2][4][2];
    #pragma unroll
    for (int mt = 0; mt < 2; mt++)
        #pragma unroll
        for (int nt = 0; nt < 4; nt++) {
            #pragma unroll
            for (int i = 0; i < 4; i++) acc[mt][nt][i] = 0.f;
            acch[mt][nt][0] = 0u; acch[mt][nt][1] = 0u;
        }

    load_stage(0, 0); CP_COMMIT();
    load_stage(1, 1); CP_COMMIT();
    load_stage(2, 2); CP_COMMIT();

    const uint32_t aRowOff = (uint32_t)((warpM * 32 + (lid & 15)) * ROW_BYTES + ((lid >> 4) << 4));
    const uint32_t bRowOff = (uint32_t)((warpN * 32 + (lid & 15)) * ROW_BYTES + ((lid >> 4) << 4));

    for (int c = 0; c < NCHUNK; ++c) {
        CP_WAIT(2);
        __syncthreads();
        if (c + 3 < NCHUNK) load_stage(c + 3, (c + 3) & 3);
        CP_COMMIT();

        const uint32_t stage = sb + (uint32_t)(c & 3) * STAGE_BYTES;
        #pragma unroll
        for (int kh = 0; kh < 2; kh++) {
            const uint32_t kb = (uint32_t)(kh * 32);
            uint32_t a[2][4], bh[2][4], bl[2][4];
            #pragma unroll
            for (int mt = 0; mt < 2; mt++)
                LDSM_X4(a[mt], stage + A_OFF + aRowOff + (uint32_t)(mt * 16 * ROW_BYTES) + kb);
            #pragma unroll
            for (int g = 0; g < 2; g++) {
                LDSM_X4(bh[g], stage + BH_OFF + bRowOff + (uint32_t)(g * 16 * ROW_BYTES) + kb);
                LDSM_X4(bl[g], stage + BL_OFF + bRowOff + (uint32_t)(g * 16 * ROW_BYTES) + kb);
            }
            #pragma unroll
            for (int mt = 0; mt < 2; mt++)
                #pragma unroll
                for (int nt = 0; nt < 4; nt++) {
                    const int g = nt >> 1, h = nt & 1;
                    mma_f32acc(acc[mt][nt], a[mt], bh[g][h], bh[g][h + 2]);
                }
            #pragma unroll
            for (int mt = 0; mt < 2; mt++)
                #pragma unroll
                for (int nt = 0; nt < 4; nt++) {
                    const int g = nt >> 1, h = nt & 1;
                    mma_f16acc(acch[mt][nt], a[mt], bl[g][h], bl[g][h + 2]);
                }
        }
    }

    // ---- epilogue: merge lo acc, bias + relu + residual (fp16 residual from A) ----
    const int lane4 = lid >> 2;
    const int lanec = (lid & 3) * 2;
    float2 bv[4];
    #pragma unroll
    for (int nt = 0; nt < 4; nt++)
        bv[nt] = *(const float2*)(bias + blockCol + warpN * 32 + nt * 8 + lanec);

    #pragma unroll
    for (int mt = 0; mt < 2; mt++) {
        const int r0 = blockRow + warpM * 32 + mt * 16 + lane4;
        const int r1 = r0 + 8;
        #pragma unroll
        for (int nt = 0; nt < 4; nt++) {
            const int col = blockCol + warpN * 32 + nt * 8 + lanec;
            const size_t o0 = (size_t)r0 * F_DIM + col;
            const size_t o1 = (size_t)r1 * F_DIM + col;
            float2 h0 = __half22float2(*(const __half2*)(A + o0));
            float2 h1 = __half22float2(*(const __half2*)(A + o1));
            float* a4 = acc[mt][nt];
            __half2 c0 = *(__half2*)&acch[mt][nt][0];
            __half2 c1 = *(__half2*)&acch[mt][nt][1];
            float s0 = a4[0] + __low2float(c0);
            float s1 = a4[1] + __high2float(c0);
            float s2 = a4[2] + __low2float(c1);
            float s3 = a4[3] + __high2float(c1);
            float2 y0, y1;
            y0.x = fmaxf(s0 + bv[nt].x, 0.f) + h0.x;
            y0.y = fmaxf(s1 + bv[nt].y, 0.f) + h0.y;
            y1.x = fmaxf(s2 + bv[nt].x, 0.f) + h1.x;
            y1.y = fmaxf(s3 + bv[nt].y, 0.f) + h1.y;
            *(float2*)(Y + o0) = y0;
            *(float2*)(Y + o1) = y1;
        }
    }
}

// ---------------- LayerNorm: pointer-parameterized ----------------
__global__ void ln_kernel(const float* __restrict__ Yin, float* __restrict__ OutF32,
                          __half* __restrict__ OutH, int last) {
    const int row = blockIdx.x;
    const size_t base4 = (size_t)row * (F_DIM / 4);
    float4 v = ((const float4*)Yin)[base4 + threadIdx.x];
    float s  = v.x + v.y + v.z + v.w;
    float ss = v.x * v.x + v.y * v.y + v.z * v.z + v.w * v.w;
    #pragma unroll
    for (int o = 16; o > 0; o >>= 1) {
        s  += __shfl_down_sync(0xffffffffu, s,  o);
        ss += __shfl_down_sync(0xffffffffu, ss, o);
    }
    __shared__ float sh_s[8], sh_ss[8];
    const int warp = threadIdx.x >> 5, lane = threadIdx.x & 31;
    if (lane == 0) { sh_s[warp] = s; sh_ss[warp] = ss; }
    __syncthreads();
    float st = 0.f, sst = 0.f;
    #pragma unroll
    for (int w = 0; w < 8; w++) { st += sh_s[w]; sst += sh_ss[w]; }
    const float inv = 1.0f / (float)F_DIM;
    const float mu  = st * inv;
    const float var = sst * inv - mu * mu;
    const float r   = rsqrtf(var + 1e-5f);
    v.x = (v.x - mu) * r; v.y = (v.y - mu) * r;
    v.z = (v.z - mu) * r; v.w = (v.w - mu) * r;
    if (last) {
        ((float4*)OutF32)[base4 + threadIdx.x] = v;
    } else {
        __half2 p0{__float2half(v.x), __float2half(v.y)};
        __half2 p1{__float2half(v.z), __float2half(v.w)};
        uint2 u;
        u.x = *(uint32_t*)&p0; u.y = *(uint32_t*)&p1;
        ((uint2*)OutH)[base4 + threadIdx.x] = u;
    }
}

// ---------------- launch: 4-way row-quarter pipelines across streams ----------------
extern "C" void kernel_launch(void* const* d_in, const int* in_sizes, int n_in,
                              void* d_out, int out_size) {
    const float* x    = (const float*)d_in[0];   // (16384, 1024)
    const float* adj  = (const float*)d_in[1];   // (1024, 1024)
    const float* W    = (const float*)d_in[2];   // (5, 1024, 1024)
    const float* bias = (const float*)d_in[3];   // (5, 1024)
    float* out = (float*)d_out;

    cudaFuncSetAttribute(gemm_mma_kernel,
                         cudaFuncAttributeMaxDynamicSharedMemorySize, SMEM_TOTAL);

    static cudaStream_t st[NPIPE] = {nullptr, nullptr, nullptr, nullptr};  // st[0] = default
    static cudaEvent_t evFork = nullptr;
    static cudaEvent_t evJoin[NPIPE] = {nullptr, nullptr, nullptr, nullptr};
    if (!evFork) {
        cudaEventCreateWithFlags(&evFork, cudaEventDisableTiming);
        for (int q = 1; q < NPIPE; ++q) {
            cudaStreamCreateWithFlags(&st[q], cudaStreamNonBlocking);
            cudaEventCreateWithFlags(&evJoin[q], cudaEventDisableTiming);
        }
    }

    __half *bh, *bl, *ah;
    float *bufA;
    cudaGetSymbolAddress((void**)&bh,   g_Bh);
    cudaGetSymbolAddress((void**)&bl,   g_Bl);
    cudaGetSymbolAddress((void**)&ah,   g_A);
    cudaGetSymbolAddress((void**)&bufA, g_bufA);

    // prep on default stream, then fork
    prep_kernel<<<dim3(F_DIM / 32, F_DIM / 32, L_LAYERS), dim3(32, 8)>>>(W, adj);
    cudaEventRecord(evFork, 0);
    for (int q = 1; q < NPIPE; ++q) cudaStreamWaitEvent(st[q], evFork, 0);

    const size_t q4 = (size_t)M_QUART * F_DIM / 4;   // float4 units per quarter
    const dim3 grid(F_DIM / BN, M_QUART / BM);       // (8, 32)

    for (int q = 0; q < NPIPE; ++q) {
        cudaStream_t sq = st[q];   // q==0 -> default (nullptr)
        const size_t roff = (size_t)q * M_QUART * F_DIM;
        tohalf_kernel<<<(int)(q4 / 256), 256, 0, sq>>>(x, (size_t)q * q4);
        for (int l = 0; l < L_LAYERS; ++l) {
            const size_t bo = (size_t)l * F_DIM * F_DIM;
            const float* bias_l = bias + (size_t)l * F_DIM;
            const int last = (l == L_LAYERS - 1);
            gemm_mma_kernel<<<grid, THREADS, SMEM_TOTAL, sq>>>(
                ah + roff, bh + bo, bl + bo, bias_l, bufA + roff);
            ln_kernel<<<M_QUART, 256, 0, sq>>>(bufA + roff,
                                               last ? (out + roff) : nullptr,
                                               ah + roff, last);
        }
    }

    // join side pipelines into default stream
    for (int q = 1; q < NPIPE; ++q) {
        cudaEventRecord(evJoin[q], st[q]);
        cudaStreamWaitEvent(0, evJoin[q], 0);
    }
}